// round 4
// baseline (speedup 1.0000x reference)
#include <cuda_runtime.h>

#define N_NODES 100000
#define E_EDGES 1600000
#define NB_SCAN 98   // ceil(100000/1024)

// ---------------- scratch (device globals; no allocations allowed) ----------
__device__ int   g_is64;
__device__ int   g_row[E_EDGES];
__device__ int   g_col[E_EDGES];
__device__ int   g_degi[N_NODES];        // in-degree (edges only)
__device__ int   g_scan[N_NODES];        // per-block inclusive scan of deg
__device__ int   g_part[NB_SCAN];        // per-block total sums
__device__ int   g_start[N_NODES];       // CSR offsets (exclusive)
__device__ int   g_cur[N_NODES];         // fill cursors
__device__ int   g_csr[E_EDGES];         // source node per in-edge, grouped by target
__device__ float g_dinv[N_NODES];
__device__ float g_s2[N_NODES * 32];     // dinv[v] * (h1[v] @ W2)
__device__ float g_a[N_NODES * 16];      // h2[v] @ Wm1[0:32]
__device__ float g_c[N_NODES * 16];      // h2[v] @ Wm1[32:64]

// ---------------- kernels ----------------------------------------------------

// Block 0: detect int64 vs int32 edge_index. Other blocks: zero g_degi.
__global__ void k_zero_detect(const int* ei32) {
    if (blockIdx.x == 0) {
        __shared__ int s_any;
        if (threadIdx.x == 0) s_any = 0;
        __syncthreads();
        int v = 0;
        for (int i = threadIdx.x; i < 1024; i += blockDim.x)
            v |= ei32[2 * i + 1];
        if (v) atomicOr(&s_any, 1);
        __syncthreads();
        if (threadIdx.x == 0) g_is64 = (s_any == 0) ? 1 : 0;
    } else {
        int i = (blockIdx.x - 1) * 256 + threadIdx.x;
        if (i < N_NODES) g_degi[i] = 0;
    }
}

// Convert indices to int32 and count in-degree on col.
__global__ void k_convert(const void* ei) {
    int e = blockIdx.x * blockDim.x + threadIdx.x;
    if (e >= E_EDGES) return;
    int r, c;
    if (g_is64) {
        const long long* p = (const long long*)ei;
        r = (int)p[e];
        c = (int)p[E_EDGES + e];
    } else {
        const int* p = (const int*)ei;
        r = p[e];
        c = p[E_EDGES + e];
    }
    g_row[e] = r;
    g_col[e] = c;
    atomicAdd(&g_degi[c], 1);
}

// Per-1024-block inclusive scan of g_degi via shuffles (2-level).
__global__ void k_scan1() {
    __shared__ int ws[32];
    int lane = threadIdx.x & 31;
    int warp = threadIdx.x >> 5;
    int i = blockIdx.x * 1024 + threadIdx.x;
    int s = (i < N_NODES) ? g_degi[i] : 0;
#pragma unroll
    for (int o = 1; o < 32; o <<= 1) {
        int t = __shfl_up_sync(0xffffffffu, s, o);
        if (lane >= o) s += t;
    }
    if (lane == 31) ws[warp] = s;
    __syncthreads();
    if (warp == 0) {
        int w = ws[lane];
#pragma unroll
        for (int o = 1; o < 32; o <<= 1) {
            int t = __shfl_up_sync(0xffffffffu, w, o);
            if (lane >= o) w += t;
        }
        ws[lane] = w;
    }
    __syncthreads();
    int incl = s + (warp ? ws[warp - 1] : 0);
    if (i < N_NODES) g_scan[i] = incl;
    if (threadIdx.x == 1023) g_part[blockIdx.x] = incl;
}

// Merged scan2+scan3: every block redundantly scans the 98 block partials
// in shared (trivial), then finalizes CSR offsets / cursors / dinv.
__global__ void k_scan23() {
    __shared__ int sp[128];
    int tid = threadIdx.x;
    if (tid < 128) sp[tid] = (tid < NB_SCAN) ? g_part[tid] : 0;
    __syncthreads();
#pragma unroll
    for (int d = 1; d < 128; d <<= 1) {
        int t = (tid < 128 && tid >= d) ? sp[tid - d] : 0;
        __syncthreads();
        if (tid < 128) sp[tid] += t;
        __syncthreads();
    }
    int v = blockIdx.x * blockDim.x + tid;
    if (v >= N_NODES) return;
    int blk = v >> 10;
    int excl = blk ? sp[blk - 1] : 0;
    int deg = g_degi[v];
    int st = g_scan[v] - deg + excl;
    g_start[v] = st;
    g_cur[v]   = st;
    g_dinv[v]  = rsqrtf((float)deg + 1.0f);
}

// Scatter edges into CSR (grouped by target node).
__global__ void k_fill() {
    int e = blockIdx.x * blockDim.x + threadIdx.x;
    if (e >= E_EDGES) return;
    int c = g_col[e];
    int idx = atomicAdd(&g_cur[c], 1);
    g_csr[idx] = g_row[e];
}

// Per node (warp): aggregate t = sum dinv[r]*x[r] over in-edges,
//   pre1 = dinv*t + dinv^2*x ; h1 = relu(pre1@W1+b1) [64] ; s2 = dinv*(h1@W2) [32]
__global__ void k_node1(const float* __restrict__ x,
                        const float* __restrict__ W1,
                        const float* __restrict__ b1,
                        const float* __restrict__ W2) {
    __shared__ float sW1[128], sb1[64], sW2[2048], sh[8][64];
    for (int i = threadIdx.x; i < 128;  i += 256) sW1[i] = W1[i];
    for (int i = threadIdx.x; i < 64;   i += 256) sb1[i] = b1[i];
    for (int i = threadIdx.x; i < 2048; i += 256) sW2[i] = W2[i];
    __syncthreads();

    int warp = threadIdx.x >> 5;
    int lane = threadIdx.x & 31;
    int v = blockIdx.x * 8 + warp;
    if (v >= N_NODES) return;

    int start = g_start[v];
    int deg   = g_degi[v];
    float a0 = 0.0f, a1 = 0.0f;
    for (int i = lane; i < deg; i += 32) {
        int r = g_csr[start + i];
        float dr = g_dinv[r];
        float2 xr = ((const float2*)x)[r];
        a0 = fmaf(dr, xr.x, a0);
        a1 = fmaf(dr, xr.y, a1);
    }
#pragma unroll
    for (int o = 16; o; o >>= 1) {
        a0 += __shfl_xor_sync(0xffffffffu, a0, o);
        a1 += __shfl_xor_sync(0xffffffffu, a1, o);
    }

    float dinv = g_dinv[v];
    float2 xv = ((const float2*)x)[v];
    float p0 = dinv * a0 + dinv * dinv * xv.x;
    float p1 = dinv * a1 + dinv * dinv * xv.y;

    float ha = fmaxf(fmaf(p0, sW1[lane],      fmaf(p1, sW1[64 + lane],      sb1[lane])),      0.0f);
    float hb = fmaxf(fmaf(p0, sW1[lane + 32], fmaf(p1, sW1[64 + lane + 32], sb1[lane + 32])), 0.0f);
    sh[warp][lane]      = ha;
    sh[warp][lane + 32] = hb;
    __syncwarp();

    float acc = 0.0f;
#pragma unroll 16
    for (int j = 0; j < 64; j++)
        acc = fmaf(sh[warp][j], sW2[j * 32 + lane], acc);
    g_s2[v * 32 + lane] = dinv * acc;
}

// Per node (warp, 8 rows in flight): 8 subgroups of 4 lanes. Subgroup `sub`
// walks edges sub, sub+8, ...; lane q in subgroup holds dims 8q..8q+7 via two
// float4 loads (contiguous 128B per row). 3-level xor-shuffle reduce, then
// h2 = relu(dinv*(agg+s2[v])+b2) and the two 32x16 Wm1 half-products.
__global__ void k_node2(const float* __restrict__ b2,
                        const float* __restrict__ Wm1) {
    __shared__ float sWm1[1056], sb2[32], sh[8][32];
    for (int i = threadIdx.x; i < 1056; i += 256) sWm1[i] = Wm1[i];
    if (threadIdx.x < 32) sb2[threadIdx.x] = b2[threadIdx.x];
    __syncthreads();

    int warp = threadIdx.x >> 5;
    int lane = threadIdx.x & 31;
    int v = blockIdx.x * 8 + warp;
    if (v >= N_NODES) return;

    int sub = lane >> 2;        // 0..7
    int q   = lane & 3;         // 0..3  -> dims 8q..8q+7
    int start = g_start[v];
    int deg   = g_degi[v];

    float4 A = make_float4(0.f, 0.f, 0.f, 0.f);
    float4 B = make_float4(0.f, 0.f, 0.f, 0.f);
    for (int i = sub; i < deg; i += 8) {
        int r = g_csr[start + i];
        const float4* p = (const float4*)g_s2 + r * 8 + q * 2;
        float4 u = p[0];
        float4 w = p[1];
        A.x += u.x; A.y += u.y; A.z += u.z; A.w += u.w;
        B.x += w.x; B.y += w.y; B.z += w.z; B.w += w.w;
    }
#pragma unroll
    for (int o = 4; o <= 16; o <<= 1) {
        A.x += __shfl_xor_sync(0xffffffffu, A.x, o);
        A.y += __shfl_xor_sync(0xffffffffu, A.y, o);
        A.z += __shfl_xor_sync(0xffffffffu, A.z, o);
        A.w += __shfl_xor_sync(0xffffffffu, A.w, o);
        B.x += __shfl_xor_sync(0xffffffffu, B.x, o);
        B.y += __shfl_xor_sync(0xffffffffu, B.y, o);
        B.z += __shfl_xor_sync(0xffffffffu, B.z, o);
        B.w += __shfl_xor_sync(0xffffffffu, B.w, o);
    }

    if (sub == 0) {
        float dinv = g_dinv[v];
        const float4* po = (const float4*)g_s2 + v * 8 + q * 2;
        float4 o1 = po[0];
        float4 o2 = po[1];
        int d = 8 * q;
        sh[warp][d]     = fmaxf(fmaf(dinv, A.x + o1.x, sb2[d]),     0.0f);
        sh[warp][d + 1] = fmaxf(fmaf(dinv, A.y + o1.y, sb2[d + 1]), 0.0f);
        sh[warp][d + 2] = fmaxf(fmaf(dinv, A.z + o1.z, sb2[d + 2]), 0.0f);
        sh[warp][d + 3] = fmaxf(fmaf(dinv, A.w + o1.w, sb2[d + 3]), 0.0f);
        sh[warp][d + 4] = fmaxf(fmaf(dinv, B.x + o2.x, sb2[d + 4]), 0.0f);
        sh[warp][d + 5] = fmaxf(fmaf(dinv, B.y + o2.y, sb2[d + 5]), 0.0f);
        sh[warp][d + 6] = fmaxf(fmaf(dinv, B.z + o2.z, sb2[d + 6]), 0.0f);
        sh[warp][d + 7] = fmaxf(fmaf(dinv, B.w + o2.w, sb2[d + 7]), 0.0f);
    }
    __syncwarp();

    int k = lane & 15;
    int rowbase = (lane < 16) ? 0 : 32;
    float r2 = 0.0f;
#pragma unroll
    for (int j = 0; j < 32; j++)
        r2 = fmaf(sh[warp][j], sWm1[(rowbase + j) * 16 + k], r2);
    if (lane < 16) g_a[v * 16 + k] = r2;
    else           g_c[v * 16 + k] = r2;
}

// Per edge (4 lanes, 4 dims/lane via float4): hm = relu(a[r]+c[cl]+ea@Wm1[64:66]+bm1),
// out = hm@Wm2+bm2 via 4-wide butterfly reduce.
__global__ void k_edge(const float* __restrict__ ea,
                       const float* __restrict__ Wm1,
                       const float* __restrict__ bm1,
                       const float* __restrict__ Wm2,
                       const float* __restrict__ bm2,
                       float* __restrict__ out) {
    __shared__ float sW64[16], sW65[16], sbm1[16], sWm2[16], sbm2;
    if (threadIdx.x < 16) {
        sW64[threadIdx.x] = Wm1[64 * 16 + threadIdx.x];
        sW65[threadIdx.x] = Wm1[65 * 16 + threadIdx.x];
        sbm1[threadIdx.x] = bm1[threadIdx.x];
        sWm2[threadIdx.x] = Wm2[threadIdx.x];
    }
    if (threadIdx.x == 0) sbm2 = bm2[0];
    __syncthreads();

    int t = blockIdx.x * blockDim.x + threadIdx.x;
    int e = t >> 2;
    int g = t & 3;              // dims 4g..4g+3
    if (e >= E_EDGES) return;

    int r = g_row[e], cl = g_col[e];
    float2 eav = ((const float2*)ea)[e];
    float4 av = ((const float4*)g_a)[r * 4 + g];
    float4 cv = ((const float4*)g_c)[cl * 4 + g];

    int k = 4 * g;
    float hm0 = fmaxf(fmaf(eav.x, sW64[k],     fmaf(eav.y, sW65[k],     av.x + cv.x + sbm1[k])),     0.0f);
    float hm1 = fmaxf(fmaf(eav.x, sW64[k + 1], fmaf(eav.y, sW65[k + 1], av.y + cv.y + sbm1[k + 1])), 0.0f);
    float hm2 = fmaxf(fmaf(eav.x, sW64[k + 2], fmaf(eav.y, sW65[k + 2], av.z + cv.z + sbm1[k + 2])), 0.0f);
    float hm3 = fmaxf(fmaf(eav.x, sW64[k + 3], fmaf(eav.y, sW65[k + 3], av.w + cv.w + sbm1[k + 3])), 0.0f);

    float p = fmaf(hm0, sWm2[k], fmaf(hm1, sWm2[k + 1], fmaf(hm2, sWm2[k + 2], hm3 * sWm2[k + 3])));
    p += __shfl_xor_sync(0xffffffffu, p, 2, 4);
    p += __shfl_xor_sync(0xffffffffu, p, 1, 4);
    if (g == 0) out[e] = p + sbm2;
}

// ---------------- launch ------------------------------------------------------

extern "C" void kernel_launch(void* const* d_in, const int* in_sizes, int n_in,
                              void* d_out, int out_size) {
    const float* x   = (const float*)d_in[0];
    const void*  ei  = d_in[1];
    const float* ea  = (const float*)d_in[2];
    const float* W1  = (const float*)d_in[3];
    const float* b1  = (const float*)d_in[4];
    const float* W2  = (const float*)d_in[5];
    const float* b2  = (const float*)d_in[6];
    const float* Wm1 = (const float*)d_in[7];
    const float* bm1 = (const float*)d_in[8];
    const float* Wm2 = (const float*)d_in[9];
    const float* bm2 = (const float*)d_in[10];
    float* out = (float*)d_out;

    k_zero_detect<<<(N_NODES + 255) / 256 + 1, 256>>>((const int*)ei);
    k_convert<<<(E_EDGES + 255) / 256, 256>>>(ei);
    k_scan1<<<NB_SCAN, 1024>>>();
    k_scan23<<<(N_NODES + 255) / 256, 256>>>();
    k_fill<<<(E_EDGES + 255) / 256, 256>>>();
    k_node1<<<(N_NODES + 7) / 8, 256>>>(x, W1, b1, W2);
    k_node2<<<(N_NODES + 7) / 8, 256>>>(b2, Wm1);
    {
        long long threads = (long long)E_EDGES * 4;
        k_edge<<<(unsigned)((threads + 255) / 256), 256>>>(ea, Wm1, bm1, Wm2, bm2, out);
    }
}